// round 2
// baseline (speedup 1.0000x reference)
#include <cuda_runtime.h>

#define NT   256
#define TT   512
#define ROWP 68      // padded row stride (floats) for 16x64 tiles
#define TRP  17      // padded stride for transposed xk (64x16)

__global__ __launch_bounds__(NT, 1)
void ttt_kernel(const float* __restrict__ XQ, const float* __restrict__ XK,
                const float* __restrict__ XV, const float* __restrict__ W1,
                const float* __restrict__ b1, const float* __restrict__ gam,
                const float* __restrict__ bet, float* __restrict__ out)
{
    __shared__ float W[4096];          // W[d*64+f], carried across steps
    __shared__ float xq_s[16*ROWP];
    __shared__ float xk_s[16*ROWP];
    __shared__ float xkT_s[64*TRP];    // xkT[d*17+k]
    __shared__ float gz_s[16*ROWP];
    __shared__ float a_s[256];         // (xq@xk^T + 1)[k][kp]
    __shared__ float bb[64];           // carried bias
    __shared__ float eta_s[16];

    const int tid = threadIdx.x;
    const int bh  = blockIdx.x;
    const int h   = bh & 15;
    const int k   = tid >> 4;          // token row 0..15
    const int q   = tid & 15;
    const int f0  = q << 2;            // feature base (4 per thread)

    const size_t base = (size_t)bh * (TT * 1024);
    const float* xqg = XQ + base;
    const float* xkg = XK + base;
    const float* xvg = XV + base;
    float*       og  = out + base;

    // ---- init carried state ----
    {
        const float* Wg = W1 + (size_t)h * 4096;
        #pragma unroll
        for (int i = 0; i < 4; i++)
            *(float4*)&W[i*1024 + tid*4] = *(const float4*)&Wg[i*1024 + tid*4];
        if (tid < 16)
            *(float4*)&bb[tid*4] = *(const float4*)&b1[h*64 + tid*4];
    }
    const float4 g4  = *(const float4*)&gam[h*64 + f0];
    const float4 be4 = *(const float4*)&bet[h*64 + f0];

    // prefetch tiles for t=0 (tid*4 == k*64 + f0)
    float4 q4 = *(const float4*)&xqg[tid*4];
    float4 k4 = *(const float4*)&xkg[tid*4];
    float4 v4 = *(const float4*)&xvg[tid*4];

    for (int t = 0; t < TT; t++) {
        // ---- phase 1: stage tiles + eta ----
        *(float4*)&xq_s[k*ROWP + f0] = q4;
        *(float4*)&xk_s[k*ROWP + f0] = k4;
        xkT_s[(f0+0)*TRP + k] = k4.x;
        xkT_s[(f0+1)*TRP + k] = k4.y;
        xkT_s[(f0+2)*TRP + k] = k4.z;
        xkT_s[(f0+3)*TRP + k] = k4.w;

        float ss = k4.x*k4.x + k4.y*k4.y + k4.z*k4.z + k4.w*k4.w;
        ss += __shfl_xor_sync(~0u, ss, 8);
        ss += __shfl_xor_sync(~0u, ss, 4);
        ss += __shfl_xor_sync(~0u, ss, 2);
        ss += __shfl_xor_sync(~0u, ss, 1);
        if (q == 0) eta_s[k] = 0.01f / (1.0f + fmaxf(sqrtf(ss), 1e-6f));
        __syncthreads();                                   // S1

        // ---- prefetch next step's tiles (hide DRAM under compute) ----
        float4 nq4 = make_float4(0.f,0.f,0.f,0.f), nk4 = nq4, nv4 = nq4;
        if (t + 1 < TT) {
            const size_t off = (size_t)(t+1)*1024 + tid*4;
            nq4 = *(const float4*)&xqg[off];
            nk4 = *(const float4*)&xkg[off];
            nv4 = *(const float4*)&xvg[off];
        }

        float em = 0.f;
        #pragma unroll
        for (int i = 0; i < 16; i++) em += eta_s[i];
        em *= (1.0f/16.0f);
        const float el = eta_s[15];

        // ---- fused matmuls: Z1 = xk@W + b,  zd_pre = xq@W + b (shares W reads) ----
        float4 z  = *(const float4*)&bb[f0];
        float4 zd = z;
        #pragma unroll 16
        for (int d = 0; d < 64; d++) {
            const float4 w4 = *(const float4*)&W[d*64 + f0];
            const float xkd = xk_s[k*ROWP + d];
            const float xqd = xq_s[k*ROWP + d];
            z.x  = fmaf(xkd, w4.x, z.x);   z.y  = fmaf(xkd, w4.y, z.y);
            z.z  = fmaf(xkd, w4.z, z.z);   z.w  = fmaf(xkd, w4.w, z.w);
            zd.x = fmaf(xqd, w4.x, zd.x);  zd.y = fmaf(xqd, w4.y, zd.y);
            zd.z = fmaf(xqd, w4.z, zd.z);  zd.w = fmaf(xqd, w4.w, zd.w);
        }

        // ---- LN(Z1) -> grad_Z1 = 2*(ln(Z1) - (xv - xk)) ----
        float s1 = z.x + z.y + z.z + z.w;
        s1 += __shfl_xor_sync(~0u, s1, 8);
        s1 += __shfl_xor_sync(~0u, s1, 4);
        s1 += __shfl_xor_sync(~0u, s1, 2);
        s1 += __shfl_xor_sync(~0u, s1, 1);
        const float mu = s1 * 0.015625f;
        const float d0 = z.x - mu, d1 = z.y - mu, d2 = z.z - mu, d3 = z.w - mu;
        float s2 = d0*d0 + d1*d1 + d2*d2 + d3*d3;
        s2 += __shfl_xor_sync(~0u, s2, 8);
        s2 += __shfl_xor_sync(~0u, s2, 4);
        s2 += __shfl_xor_sync(~0u, s2, 2);
        s2 += __shfl_xor_sync(~0u, s2, 1);
        const float r = rsqrtf(s2 * 0.015625f + 1e-6f);
        float4 gz;
        gz.x = 2.0f * (fmaf(g4.x, d0*r, be4.x) - v4.x + k4.x);
        gz.y = 2.0f * (fmaf(g4.y, d1*r, be4.y) - v4.y + k4.y);
        gz.z = 2.0f * (fmaf(g4.z, d2*r, be4.z) - v4.z + k4.z);
        gz.w = 2.0f * (fmaf(g4.w, d3*r, be4.w) - v4.w + k4.w);
        *(float4*)&gz_s[k*ROWP + f0] = gz;

        // ---- A' = xq@xk^T + 1 (the +1 folds grad_b1 into the correction) ----
        float a = 1.0f;
        #pragma unroll 16
        for (int d = 0; d < 64; d++)
            a = fmaf(xq_s[k*ROWP + d], xkT_s[d*TRP + q], a);
        a_s[tid] = a;
        __syncthreads();                                   // S2

        // ---- correction: Z1d = zd_pre - em * (A' @ gz) ----
        float4 c = make_float4(0.f,0.f,0.f,0.f);
        #pragma unroll
        for (int kp = 0; kp < 16; kp++) {
            const float av  = a_s[k*16 + kp];
            const float4 gv = *(const float4*)&gz_s[kp*ROWP + f0];
            c.x = fmaf(av, gv.x, c.x); c.y = fmaf(av, gv.y, c.y);
            c.z = fmaf(av, gv.z, c.z); c.w = fmaf(av, gv.w, c.w);
        }
        zd.x = fmaf(-em, c.x, zd.x); zd.y = fmaf(-em, c.y, zd.y);
        zd.z = fmaf(-em, c.z, zd.z); zd.w = fmaf(-em, c.w, zd.w);

        // ---- LN(Z1d), out = xq + ln ----
        float t1 = zd.x + zd.y + zd.z + zd.w;
        t1 += __shfl_xor_sync(~0u, t1, 8);
        t1 += __shfl_xor_sync(~0u, t1, 4);
        t1 += __shfl_xor_sync(~0u, t1, 2);
        t1 += __shfl_xor_sync(~0u, t1, 1);
        const float mu2 = t1 * 0.015625f;
        const float e0 = zd.x - mu2, e1 = zd.y - mu2, e2 = zd.z - mu2, e3 = zd.w - mu2;
        float t2 = e0*e0 + e1*e1 + e2*e2 + e3*e3;
        t2 += __shfl_xor_sync(~0u, t2, 8);
        t2 += __shfl_xor_sync(~0u, t2, 4);
        t2 += __shfl_xor_sync(~0u, t2, 2);
        t2 += __shfl_xor_sync(~0u, t2, 1);
        const float r2 = rsqrtf(t2 * 0.015625f + 1e-6f);
        float4 o;
        o.x = q4.x + fmaf(g4.x, e0*r2, be4.x);
        o.y = q4.y + fmaf(g4.y, e1*r2, be4.y);
        o.z = q4.z + fmaf(g4.z, e2*r2, be4.z);
        o.w = q4.w + fmaf(g4.w, e3*r2, be4.w);
        *(float4*)&og[(size_t)t*1024 + tid*4] = o;

        __syncthreads();                                   // S3 (all W/gz reads done)

        // ---- carry update: rank-1 (last token only) ----
        {
            const float4 gl = *(const float4*)&gz_s[15*ROWP + f0];
            #pragma unroll
            for (int j = 0; j < 4; j++) {
                const int d = k + 16*j;
                const float cf = -el * xk_s[15*ROWP + d];
                float4 w4 = *(float4*)&W[d*64 + f0];
                w4.x = fmaf(cf, gl.x, w4.x); w4.y = fmaf(cf, gl.y, w4.y);
                w4.z = fmaf(cf, gl.z, w4.z); w4.w = fmaf(cf, gl.w, w4.w);
                *(float4*)&W[d*64 + f0] = w4;
            }
            if (tid < 16) {   // k==0, f0 == tid*4, gl is gz_s[15][f0]
                float4 bv = *(float4*)&bb[f0];
                bv.x = fmaf(-el, gl.x, bv.x); bv.y = fmaf(-el, gl.y, bv.y);
                bv.z = fmaf(-el, gl.z, bv.z); bv.w = fmaf(-el, gl.w, bv.w);
                *(float4*)&bb[f0] = bv;
            }
        }
        __syncthreads();                                   // S4 (update visible)

        q4 = nq4; k4 = nk4; v4 = nv4;
    }
}

extern "C" void kernel_launch(void* const* d_in, const int* in_sizes, int n_in,
                              void* d_out, int out_size) {
    const float* XQ  = (const float*)d_in[0];
    const float* XK  = (const float*)d_in[1];
    const float* XV  = (const float*)d_in[2];
    const float* W1  = (const float*)d_in[3];
    const float* b1  = (const float*)d_in[4];
    const float* gam = (const float*)d_in[5];
    const float* bet = (const float*)d_in[6];
    float* out = (float*)d_out;

    const int nbh = in_sizes[0] / (TT * 16 * 64);   // B*H = 64
    ttt_kernel<<<nbh, NT>>>(XQ, XK, XV, W1, b1, gam, bet, out);
}